// round 11
// baseline (speedup 1.0000x reference)
#include <cuda_runtime.h>
#include <cuda_fp16.h>
#include <cstdint>
#include <math.h>

// Problem shape (fixed)
#define Bb  4
#define Kk  8192
#define Dd  1024
#define Mm  (Bb * Kk)          // 32768 GEMM rows
#define NCH 128                // scan chunks along K
#define LCH (Kk / NCH)         // 64 steps per chunk
#define CHN (Bb * Dd)          // 4096 independent channels

// Scratch (allocation-free rule: __device__ globals)
__device__ __half g_lamh[(size_t)Mm * Dd];    // 64 MiB fp16 lam
__device__ __half g_Xh[(size_t)Mm * Dd];      // 64 MiB fp16 X
__device__ __half g_Wh[(size_t)Dd * Dd];      // 2 MiB fp16 W
__device__ float  g_A[NCH * CHN];
__device__ float  g_S[NCH * CHN];
__device__ float  g_P[NCH * CHN];

// ---------------------------------------------------------------------------
// f32 -> f16 conversion, vectorized
// ---------------------------------------------------------------------------
__global__ __launch_bounds__(256) void f2h_kernel(const float4* __restrict__ src,
                                                  uint2* __restrict__ dst, int n4)
{
    int i = blockIdx.x * blockDim.x + threadIdx.x;
    const int stride = gridDim.x * blockDim.x;
    for (; i < n4; i += stride) {
        float4 v = src[i];
        __half2 h0 = __floats2half2_rn(v.x, v.y);
        __half2 h1 = __floats2half2_rn(v.z, v.w);
        uint2 o;
        o.x = *reinterpret_cast<unsigned*>(&h0);
        o.y = *reinterpret_cast<unsigned*>(&h1);
        dst[i] = o;
    }
}

// ---------------------------------------------------------------------------
// FP16 tensor-core GEMM + sigmoid epilogue:  g_lamh = sigmoid(X @ W^T + b)
// m-offset parameter so the grid can be launched in batch-halves.
// ---------------------------------------------------------------------------
#define BM 128
#define BN 256
#define BK 32
#define PITH 40
#define NSTG 4
#define A_STGH (BM * PITH)
#define B_STGH (BN * PITH)
#define SMEM_HALVES (NSTG * (A_STGH + B_STGH))
#define NKT (Dd / BK)

__device__ __forceinline__ void cp16s(uint32_t smem_dst, const void* gmem_src) {
    asm volatile("cp.async.cg.shared.global [%0], [%1], 16;\n"
                 :: "r"(smem_dst), "l"(gmem_src));
}
__device__ __forceinline__ void cp_commit() {
    asm volatile("cp.async.commit_group;\n");
}
template <int N>
__device__ __forceinline__ void cp_wait() {
    asm volatile("cp.async.wait_group %0;\n" :: "n"(N));
}
__device__ __forceinline__ void mma_f16(float* d, const unsigned* a, const unsigned* b) {
    asm volatile(
        "mma.sync.aligned.m16n8k16.row.col.f32.f16.f16.f32 "
        "{%0,%1,%2,%3}, {%4,%5,%6,%7}, {%8,%9}, {%0,%1,%2,%3};\n"
        : "+f"(d[0]), "+f"(d[1]), "+f"(d[2]), "+f"(d[3])
        : "r"(a[0]), "r"(a[1]), "r"(a[2]), "r"(a[3]), "r"(b[0]), "r"(b[1]));
}

extern __shared__ __half smemh[];

__global__ __launch_bounds__(256, 1) void gemm_sigmoid_f16(
    const float* __restrict__ bias, int moff)
{
    __half* As = smemh;
    __half* Bs = smemh + NSTG * A_STGH;

    const int tid  = threadIdx.x;
    const int lane = tid & 31;
    const int wid  = tid >> 5;
    const int wm0  = (wid & 1) * 64;
    const int wn0  = (wid >> 1) * 64;
    const int g    = lane >> 2;
    const int q    = lane & 3;
    const int m0b  = (blockIdx.y + moff) * BM;
    const int n0b  = blockIdx.x * BN;

    const uint32_t sA = (uint32_t)__cvta_generic_to_shared(As);
    const uint32_t sB = (uint32_t)__cvta_generic_to_shared(Bs);

    float acc[4][8][4];
    #pragma unroll
    for (int mi = 0; mi < 4; mi++)
        #pragma unroll
        for (int ni = 0; ni < 8; ni++)
            #pragma unroll
            for (int r = 0; r < 4; r++)
                acc[mi][ni][r] = 0.0f;

    auto load_stage = [&](int kt) {
        const int slot = kt & (NSTG - 1);
        const int k0   = kt * BK;
        const uint32_t abase = sA + slot * A_STGH * 2;
        const uint32_t bbase = sB + slot * B_STGH * 2;
        #pragma unroll
        for (int i = 0; i < 6; i++) {
            int idx = tid + i * 256;
            if (idx < 512) {
                int r = idx >> 2, c = idx & 3;
                cp16s(abase + (r * PITH + c * 8) * 2,
                      &g_Xh[(size_t)(m0b + r) * Dd + k0 + c * 8]);
            } else {
                int j = idx - 512;
                int r = j >> 2, c = j & 3;
                cp16s(bbase + (r * PITH + c * 8) * 2,
                      &g_Wh[(size_t)(n0b + r) * Dd + k0 + c * 8]);
            }
        }
        cp_commit();
    };

    load_stage(0);
    load_stage(1);
    load_stage(2);

    for (int kt = 0; kt < NKT; kt++) {
        if (kt + 3 < NKT) load_stage(kt + 3);
        else cp_commit();                  // keep group accounting exact at tail
        cp_wait<3>();
        __syncthreads();

        const int slot = kt & (NSTG - 1);
        const __half* Asl = &As[slot * A_STGH];
        const __half* Bsl = &Bs[slot * B_STGH];

        #pragma unroll
        for (int kf = 0; kf < BK; kf += 16) {
            unsigned af[4][4], bf[8][2];
            #pragma unroll
            for (int mi = 0; mi < 4; mi++) {
                int base = (wm0 + mi * 16 + g) * PITH + kf + 2 * q;
                af[mi][0] = *(const unsigned*)&Asl[base];
                af[mi][1] = *(const unsigned*)&Asl[base + 8 * PITH];
                af[mi][2] = *(const unsigned*)&Asl[base + 8];
                af[mi][3] = *(const unsigned*)&Asl[base + 8 * PITH + 8];
            }
            #pragma unroll
            for (int ni = 0; ni < 8; ni++) {
                int base = (wn0 + ni * 8 + g) * PITH + kf + 2 * q;
                bf[ni][0] = *(const unsigned*)&Bsl[base];
                bf[ni][1] = *(const unsigned*)&Bsl[base + 8];
            }
            #pragma unroll
            for (int mi = 0; mi < 4; mi++)
                #pragma unroll
                for (int ni = 0; ni < 8; ni++)
                    mma_f16(acc[mi][ni], af[mi], bf[ni]);
        }
        __syncthreads();
    }

    #pragma unroll
    for (int ni = 0; ni < 8; ni++) {
        const int c0 = n0b + wn0 + ni * 8 + 2 * q;
        const float b0 = bias[c0];
        const float b1 = bias[c0 + 1];
        #pragma unroll
        for (int mi = 0; mi < 4; mi++) {
            const int r0 = m0b + wm0 + mi * 16 + g;
            float z0 = acc[mi][ni][0] + b0, z1 = acc[mi][ni][1] + b1;
            float z2 = acc[mi][ni][2] + b0, z3 = acc[mi][ni][3] + b1;
            __half2 h0 = __floats2half2_rn(1.0f / (1.0f + __expf(-z0)),
                                           1.0f / (1.0f + __expf(-z1)));
            __half2 h1 = __floats2half2_rn(1.0f / (1.0f + __expf(-z2)),
                                           1.0f / (1.0f + __expf(-z3)));
            *(__half2*)&g_lamh[(size_t)r0 * Dd + c0]       = h0;
            *(__half2*)&g_lamh[(size_t)(r0 + 8) * Dd + c0] = h1;
        }
    }
}

// ---------------------------------------------------------------------------
// Scan phase 1 (R8 body + batch offset): 2 ch/thread, grid (2, 2, 128).
// ---------------------------------------------------------------------------
__global__ __launch_bounds__(256) void scan_phase1(int boff)
{
    const int d2 = blockIdx.x * 256 + threadIdx.x;   // 0..511
    const int d  = d2 * 2;
    const int b  = blockIdx.y + boff;
    const int c  = blockIdx.z;
    size_t base = ((size_t)(b * Kk + c * LCH)) * Dd + d;

    float s0 = 0.0f, s1 = 0.0f, A0 = 1.0f, A1 = 1.0f;
    #pragma unroll 8
    for (int k = 0; k < LCH; k++) {
        size_t idx = base + (size_t)k * Dd;
        float2 lam = __half22float2(*(const __half2*)&g_lamh[idx]);
        float2 xv  = __half22float2(*(const __half2*)&g_Xh[idx]);
        s0 = fmaf(lam.x, s0 - xv.x, xv.x);
        s1 = fmaf(lam.y, s1 - xv.y, xv.y);
        A0 *= lam.x;
        A1 *= lam.y;
    }
    const int ch = b * Dd + d;
    *(float2*)&g_A[c * CHN + ch] = make_float2(A0, A1);
    *(float2*)&g_S[c * CHN + ch] = make_float2(s0, s1);
}

// ---------------------------------------------------------------------------
// Scan phase 2 (R8 body + batch offset): 128 chunks, one warp per channel.
// ---------------------------------------------------------------------------
__global__ __launch_bounds__(256) void scan_phase2(int boff)
{
    const int lane = threadIdx.x & 31;
    const int ch   = boff * Dd + blockIdx.x * 8 + (threadIdx.x >> 5);

    float A[4], S[4];
    #pragma unroll
    for (int j = 0; j < 4; j++) {
        A[j] = g_A[(4 * lane + j) * CHN + ch];
        S[j] = g_S[(4 * lane + j) * CHN + ch];
    }
    float Ac = A[0], Sc = S[0];
    #pragma unroll
    for (int j = 1; j < 4; j++) { Sc = fmaf(A[j], Sc, S[j]); Ac *= A[j]; }

    #pragma unroll
    for (int off = 1; off < 32; off <<= 1) {
        float Ap = __shfl_up_sync(0xffffffffu, Ac, off);
        float Sp = __shfl_up_sync(0xffffffffu, Sc, off);
        if (lane >= off) { Sc = fmaf(Ac, Sp, Sc); Ac *= Ap; }
    }
    float Pbase = __shfl_up_sync(0xffffffffu, Sc, 1);
    if (lane == 0) Pbase = 0.0f;

    float s = Pbase;
    #pragma unroll
    for (int j = 0; j < 4; j++) {
        g_P[(4 * lane + j) * CHN + ch] = s;
        s = fmaf(A[j], s, S[j]);
    }
}

// ---------------------------------------------------------------------------
// Scan phase 3 (R8 body + batch offset): re-scan from prefix, write fp32 out.
// ---------------------------------------------------------------------------
__global__ __launch_bounds__(256) void scan_phase3(float* __restrict__ out, int boff)
{
    const int d2 = blockIdx.x * 256 + threadIdx.x;
    const int d  = d2 * 2;
    const int b  = blockIdx.y + boff;
    const int c  = blockIdx.z;
    const int ch = b * Dd + d;
    size_t base = ((size_t)(b * Kk + c * LCH)) * Dd + d;

    float2 p = *(const float2*)&g_P[c * CHN + ch];
    float s0 = p.x, s1 = p.y;
    #pragma unroll 8
    for (int k = 0; k < LCH; k++) {
        size_t idx = base + (size_t)k * Dd;
        float2 lam = __half22float2(*(const __half2*)&g_lamh[idx]);
        float2 xv  = __half22float2(*(const __half2*)&g_Xh[idx]);
        s0 = fmaf(lam.x, s0 - xv.x, xv.x);
        s1 = fmaf(lam.y, s1 - xv.y, xv.y);
        *(float2*)&out[idx] = make_float2(s0, s1);
    }
}

// ---------------------------------------------------------------------------
extern "C" void kernel_launch(void* const* d_in, const int* in_sizes, int n_in,
                              void* d_out, int out_size)
{
    const float* X    = (const float*)d_in[0];  // [B,K,D]
    const float* W    = (const float*)d_in[1];  // [D,D]
    const float* bias = (const float*)d_in[2];  // [D]
    float* out        = (float*)d_out;          // [B,K,D]

    // Side stream + events: created once, on the (uncaptured) correctness call.
    static cudaStream_t s2 = nullptr;
    static cudaEvent_t evFork = nullptr, evX23 = nullptr, evG0 = nullptr,
                       evJoin = nullptr;
    if (s2 == nullptr) {
        cudaStreamCreateWithFlags(&s2, cudaStreamNonBlocking);
        cudaEventCreateWithFlags(&evFork, cudaEventDisableTiming);
        cudaEventCreateWithFlags(&evX23, cudaEventDisableTiming);
        cudaEventCreateWithFlags(&evG0, cudaEventDisableTiming);
        cudaEventCreateWithFlags(&evJoin, cudaEventDisableTiming);
    }

    __half* Xh; cudaGetSymbolAddress((void**)&Xh, g_Xh);
    __half* Wh; cudaGetSymbolAddress((void**)&Wh, g_Wh);

    const int smem_bytes = SMEM_HALVES * (int)sizeof(__half);   // 120 KB
    cudaFuncSetAttribute(gemm_sigmoid_f16,
                         cudaFuncAttributeMaxDynamicSharedMemorySize, smem_bytes);

    const int half_elems = (Mm / 2) * Dd;        // X elements per batch-half

    // main: W + X(b01) conversion
    f2h_kernel<<<256, 256>>>((const float4*)W, (uint2*)Wh, (Dd * Dd) / 4);
    f2h_kernel<<<512, 256>>>((const float4*)X, (uint2*)Xh, half_elems / 4);

    // fork side stream
    cudaEventRecord(evFork, 0);
    cudaStreamWaitEvent(s2, evFork, 0);

    // s2: X(b23) conversion (overlaps GEMM half 0)
    f2h_kernel<<<512, 256, 0, s2>>>((const float4*)(X + half_elems),
                                    (uint2*)(Xh + half_elems), half_elems / 4);
    cudaEventRecord(evX23, s2);

    // main: GEMM half 0 (b01)
    dim3 gemm_grid(Dd / BN, Mm / BM / 2);        // (4, 128)
    gemm_sigmoid_f16<<<gemm_grid, 256, smem_bytes>>>(bias, 0);
    cudaEventRecord(evG0, 0);

    // main: GEMM half 1 (b23) — needs X(b23)
    cudaStreamWaitEvent(0, evX23, 0);
    gemm_sigmoid_f16<<<gemm_grid, 256, smem_bytes>>>(bias, Mm / BM / 2);

    // s2: scans for b01 (overlap GEMM half 1)
    cudaStreamWaitEvent(s2, evG0, 0);
    dim3 scan_grid(Dd / 512, 2, NCH);            // (2, 2, 128)
    scan_phase1<<<scan_grid, 256, 0, s2>>>(0);
    scan_phase2<<<CHN / 16, 256, 0, s2>>>(0);    // 256 blocks, 2048 channels
    scan_phase3<<<scan_grid, 256, 0, s2>>>(out, 0);
    cudaEventRecord(evJoin, s2);

    // main: scans for b23 (after GEMM half 1 by stream order)
    scan_phase1<<<scan_grid, 256>>>(2);
    scan_phase2<<<CHN / 16, 256>>>(2);
    scan_phase3<<<scan_grid, 256>>>(out, 2);

    // join
    cudaStreamWaitEvent(0, evJoin, 0);
}

// round 14
// speedup vs baseline: 1.0435x; 1.0435x over previous
#include <cuda_runtime.h>
#include <cuda_fp16.h>
#include <cstdint>
#include <math.h>

// Problem shape (fixed)
#define Bb  4
#define Kk  8192
#define Dd  1024
#define Mm  (Bb * Kk)          // 32768 GEMM rows
#define NCH 128                // scan chunks along K
#define LCH (Kk / NCH)         // 64 steps per chunk
#define CHN (Bb * Dd)          // 4096 independent channels

// Scratch (allocation-free rule: __device__ globals)
__device__ __half g_lamh[(size_t)Mm * Dd];    // 64 MiB fp16 lam
__device__ __half g_Xh[(size_t)Mm * Dd];      // 64 MiB fp16 X
__device__ __half g_Wh[(size_t)Dd * Dd];      // 2 MiB fp16 W
__device__ float  g_A[NCH * CHN];
__device__ float  g_S[NCH * CHN];
__device__ float  g_P[NCH * CHN];

// ---------------------------------------------------------------------------
// f32 -> f16 conversion, vectorized
// ---------------------------------------------------------------------------
__global__ __launch_bounds__(256) void f2h_kernel(const float4* __restrict__ src,
                                                  uint2* __restrict__ dst, int n4)
{
    int i = blockIdx.x * blockDim.x + threadIdx.x;
    const int stride = gridDim.x * blockDim.x;
    for (; i < n4; i += stride) {
        float4 v = src[i];
        __half2 h0 = __floats2half2_rn(v.x, v.y);
        __half2 h1 = __floats2half2_rn(v.z, v.w);
        uint2 o;
        o.x = *reinterpret_cast<unsigned*>(&h0);
        o.y = *reinterpret_cast<unsigned*>(&h1);
        dst[i] = o;
    }
}

// ---------------------------------------------------------------------------
// FP16 tensor-core GEMM + sigmoid epilogue:  g_lamh = sigmoid(X @ W^T + b)
// R8 config (256 thr, 128x256x32, 4-stage cp.async) + ldmatrix fragment loads.
// ---------------------------------------------------------------------------
#define BM 128
#define BN 256
#define BK 32
#define PITH 40
#define NSTG 4
#define A_STGH (BM * PITH)
#define B_STGH (BN * PITH)
#define SMEM_HALVES (NSTG * (A_STGH + B_STGH))
#define NKT (Dd / BK)

__device__ __forceinline__ void cp16s(uint32_t smem_dst, const void* gmem_src) {
    asm volatile("cp.async.cg.shared.global [%0], [%1], 16;\n"
                 :: "r"(smem_dst), "l"(gmem_src));
}
__device__ __forceinline__ void cp_commit() {
    asm volatile("cp.async.commit_group;\n");
}
template <int N>
__device__ __forceinline__ void cp_wait() {
    asm volatile("cp.async.wait_group %0;\n" :: "n"(N));
}
__device__ __forceinline__ void mma_f16(float* d, const unsigned* a, const unsigned* b) {
    asm volatile(
        "mma.sync.aligned.m16n8k16.row.col.f32.f16.f16.f32 "
        "{%0,%1,%2,%3}, {%4,%5,%6,%7}, {%8,%9}, {%0,%1,%2,%3};\n"
        : "+f"(d[0]), "+f"(d[1]), "+f"(d[2]), "+f"(d[3])
        : "r"(a[0]), "r"(a[1]), "r"(a[2]), "r"(a[3]), "r"(b[0]), "r"(b[1]));
}
__device__ __forceinline__ void ldsm_x4(unsigned* r, uint32_t addr) {
    asm volatile("ldmatrix.sync.aligned.m8n8.x4.shared.b16 {%0,%1,%2,%3}, [%4];"
        : "=r"(r[0]), "=r"(r[1]), "=r"(r[2]), "=r"(r[3]) : "r"(addr));
}
__device__ __forceinline__ void ldsm_x2(unsigned* r, uint32_t addr) {
    asm volatile("ldmatrix.sync.aligned.m8n8.x2.shared.b16 {%0,%1}, [%2];"
        : "=r"(r[0]), "=r"(r[1]) : "r"(addr));
}

extern __shared__ __half smemh[];

__global__ __launch_bounds__(256, 1) void gemm_sigmoid_f16(
    const float* __restrict__ bias)
{
    const int tid  = threadIdx.x;
    const int lane = tid & 31;
    const int wid  = tid >> 5;
    const int wm0  = (wid & 1) * 64;
    const int wn0  = (wid >> 1) * 64;
    const int g    = lane >> 2;
    const int q    = lane & 3;
    const int m0b  = blockIdx.y * BM;
    const int n0b  = blockIdx.x * BN;

    const uint32_t sA = (uint32_t)__cvta_generic_to_shared(smemh);
    const uint32_t sB = sA + NSTG * A_STGH * 2;

    // ldmatrix per-lane row/col offsets
    const int arow = ((lane & 8) ? 8 : 0) + (lane & 7);   // A m-row within 16
    const int akad = (lane & 16) ? 8 : 0;                 // A k offset
    const int brow = lane & 7;                            // B n-row within 8
    const int bkad = (lane & 8) ? 8 : 0;                  // B k offset

    float acc[4][8][4];
    #pragma unroll
    for (int mi = 0; mi < 4; mi++)
        #pragma unroll
        for (int ni = 0; ni < 8; ni++)
            #pragma unroll
            for (int r = 0; r < 4; r++)
                acc[mi][ni][r] = 0.0f;

    auto load_stage = [&](int kt) {
        const int slot = kt & (NSTG - 1);
        const int k0   = kt * BK;
        const uint32_t abase = sA + slot * A_STGH * 2;
        const uint32_t bbase = sB + slot * B_STGH * 2;
        #pragma unroll
        for (int i = 0; i < 6; i++) {
            int idx = tid + i * 256;
            if (idx < 512) {
                int r = idx >> 2, c = idx & 3;
                cp16s(abase + (r * PITH + c * 8) * 2,
                      &g_Xh[(size_t)(m0b + r) * Dd + k0 + c * 8]);
            } else {
                int j = idx - 512;
                int r = j >> 2, c = j & 3;
                cp16s(bbase + (r * PITH + c * 8) * 2,
                      &g_Wh[(size_t)(n0b + r) * Dd + k0 + c * 8]);
            }
        }
        cp_commit();
    };

    load_stage(0);
    load_stage(1);
    load_stage(2);

    for (int kt = 0; kt < NKT; kt++) {
        if (kt + 3 < NKT) load_stage(kt + 3);
        else cp_commit();                  // keep group accounting exact at tail
        cp_wait<3>();
        __syncthreads();

        const int slot = kt & (NSTG - 1);
        const uint32_t aslot = sA + slot * A_STGH * 2;
        const uint32_t bslot = sB + slot * B_STGH * 2;

        #pragma unroll
        for (int kf = 0; kf < BK; kf += 16) {
            unsigned af[4][4], bf[8][2];
            #pragma unroll
            for (int mi = 0; mi < 4; mi++)
                ldsm_x4(af[mi],
                        aslot + ((wm0 + mi * 16 + arow) * PITH + kf + akad) * 2);
            #pragma unroll
            for (int ni = 0; ni < 8; ni++)
                ldsm_x2(bf[ni],
                        bslot + ((wn0 + ni * 8 + brow) * PITH + kf + bkad) * 2);
            #pragma unroll
            for (int mi = 0; mi < 4; mi++)
                #pragma unroll
                for (int ni = 0; ni < 8; ni++)
                    mma_f16(acc[mi][ni], af[mi], bf[ni]);
        }
        __syncthreads();
    }

    // Epilogue: bias + sigmoid -> g_lamh (fp16, half2 stores; c0 always even)
    #pragma unroll
    for (int ni = 0; ni < 8; ni++) {
        const int c0 = n0b + wn0 + ni * 8 + 2 * q;
        const float b0 = bias[c0];
        const float b1 = bias[c0 + 1];
        #pragma unroll
        for (int mi = 0; mi < 4; mi++) {
            const int r0 = m0b + wm0 + mi * 16 + g;
            float z0 = acc[mi][ni][0] + b0, z1 = acc[mi][ni][1] + b1;
            float z2 = acc[mi][ni][2] + b0, z3 = acc[mi][ni][3] + b1;
            __half2 h0 = __floats2half2_rn(1.0f / (1.0f + __expf(-z0)),
                                           1.0f / (1.0f + __expf(-z1)));
            __half2 h1 = __floats2half2_rn(1.0f / (1.0f + __expf(-z2)),
                                           1.0f / (1.0f + __expf(-z3)));
            *(__half2*)&g_lamh[(size_t)r0 * Dd + c0]       = h0;
            *(__half2*)&g_lamh[(size_t)(r0 + 8) * Dd + c0] = h1;
        }
    }
}

// ---------------------------------------------------------------------------
// Scan phase 1: 2 ch/thread (half2), grid (2, 4, 128) = 1024 blocks.
// ---------------------------------------------------------------------------
__global__ __launch_bounds__(256) void scan_phase1()
{
    const int d2 = blockIdx.x * 256 + threadIdx.x;   // 0..511
    const int d  = d2 * 2;
    const int b  = blockIdx.y;
    const int c  = blockIdx.z;
    size_t base = ((size_t)(b * Kk + c * LCH)) * Dd + d;

    float s0 = 0.0f, s1 = 0.0f, A0 = 1.0f, A1 = 1.0f;
    #pragma unroll 8
    for (int k = 0; k < LCH; k++) {
        size_t idx = base + (size_t)k * Dd;
        float2 lam = __half22float2(*(const __half2*)&g_lamh[idx]);
        float2 xv  = __half22float2(*(const __half2*)&g_Xh[idx]);
        s0 = fmaf(lam.x, s0 - xv.x, xv.x);
        s1 = fmaf(lam.y, s1 - xv.y, xv.y);
        A0 *= lam.x;
        A1 *= lam.y;
    }
    const int ch = b * Dd + d;
    *(float2*)&g_A[c * CHN + ch] = make_float2(A0, A1);
    *(float2*)&g_S[c * CHN + ch] = make_float2(s0, s1);
}

// ---------------------------------------------------------------------------
// Scan phase 2: 128 chunks per channel; one warp per channel, 4 chunks/lane.
// ---------------------------------------------------------------------------
__global__ __launch_bounds__(256) void scan_phase2()
{
    const int lane = threadIdx.x & 31;
    const int ch   = blockIdx.x * 8 + (threadIdx.x >> 5);

    float A[4], S[4];
    #pragma unroll
    for (int j = 0; j < 4; j++) {
        A[j] = g_A[(4 * lane + j) * CHN + ch];
        S[j] = g_S[(4 * lane + j) * CHN + ch];
    }
    float Ac = A[0], Sc = S[0];
    #pragma unroll
    for (int j = 1; j < 4; j++) { Sc = fmaf(A[j], Sc, S[j]); Ac *= A[j]; }

    #pragma unroll
    for (int off = 1; off < 32; off <<= 1) {
        float Ap = __shfl_up_sync(0xffffffffu, Ac, off);
        float Sp = __shfl_up_sync(0xffffffffu, Sc, off);
        if (lane >= off) { Sc = fmaf(Ac, Sp, Sc); Ac *= Ap; }
    }
    float Pbase = __shfl_up_sync(0xffffffffu, Sc, 1);
    if (lane == 0) Pbase = 0.0f;

    float s = Pbase;
    #pragma unroll
    for (int j = 0; j < 4; j++) {
        g_P[(4 * lane + j) * CHN + ch] = s;
        s = fmaf(A[j], s, S[j]);
    }
}

// ---------------------------------------------------------------------------
// Scan phase 3: re-scan each chunk from its prefix; write fp32 output.
// ---------------------------------------------------------------------------
__global__ __launch_bounds__(256) void scan_phase3(float* __restrict__ out)
{
    const int d2 = blockIdx.x * 256 + threadIdx.x;
    const int d  = d2 * 2;
    const int b  = blockIdx.y;
    const int c  = blockIdx.z;
    const int ch = b * Dd + d;
    size_t base = ((size_t)(b * Kk + c * LCH)) * Dd + d;

    float2 p = *(const float2*)&g_P[c * CHN + ch];
    float s0 = p.x, s1 = p.y;
    #pragma unroll 8
    for (int k = 0; k < LCH; k++) {
        size_t idx = base + (size_t)k * Dd;
        float2 lam = __half22float2(*(const __half2*)&g_lamh[idx]);
        float2 xv  = __half22float2(*(const __half2*)&g_Xh[idx]);
        s0 = fmaf(lam.x, s0 - xv.x, xv.x);
        s1 = fmaf(lam.y, s1 - xv.y, xv.y);
        *(float2*)&out[idx] = make_float2(s0, s1);
    }
}

// ---------------------------------------------------------------------------
extern "C" void kernel_launch(void* const* d_in, const int* in_sizes, int n_in,
                              void* d_out, int out_size)
{
    const float* X    = (const float*)d_in[0];  // [B,K,D]
    const float* W    = (const float*)d_in[1];  // [D,D]
    const float* bias = (const float*)d_in[2];  // [D]
    float* out        = (float*)d_out;          // [B,K,D]

    __half* Xh; cudaGetSymbolAddress((void**)&Xh, g_Xh);
    __half* Wh; cudaGetSymbolAddress((void**)&Wh, g_Wh);
    f2h_kernel<<<1024, 256>>>((const float4*)X, (uint2*)Xh, (Mm * Dd) / 4);
    f2h_kernel<<<256, 256>>>((const float4*)W, (uint2*)Wh, (Dd * Dd) / 4);

    const int smem_bytes = SMEM_HALVES * (int)sizeof(__half);   // 120 KB
    cudaFuncSetAttribute(gemm_sigmoid_f16,
                         cudaFuncAttributeMaxDynamicSharedMemorySize, smem_bytes);

    dim3 gemm_grid(Dd / BN, Mm / BM);           // (4, 256)
    gemm_sigmoid_f16<<<gemm_grid, 256, smem_bytes>>>(bias);

    dim3 scan_grid(Dd / 512, Bb, NCH);          // (2, 4, 128)
    scan_phase1<<<scan_grid, 256>>>();
    scan_phase2<<<CHN / 8, 256>>>();
    scan_phase3<<<scan_grid, 256>>>(out);
}

// round 15
// speedup vs baseline: 1.0545x; 1.0105x over previous
#include <cuda_runtime.h>
#include <cuda_fp16.h>
#include <cstdint>
#include <math.h>

// Problem shape (fixed)
#define Bb  4
#define Kk  8192
#define Dd  1024
#define Mm  (Bb * Kk)          // 32768 GEMM rows
#define NCH 128                // scan chunks along K
#define LCH (Kk / NCH)         // 64 steps per chunk
#define CHN (Bb * Dd)          // 4096 independent channels

// Scratch (allocation-free rule: __device__ globals)
__device__ __half g_lamh[(size_t)Mm * Dd];    // 64 MiB fp16 lam
__device__ __half g_Xh[(size_t)Mm * Dd];      // 64 MiB fp16 X
__device__ __half g_Wh[(size_t)Dd * Dd];      // 2 MiB fp16 W
__device__ float  g_A[NCH * CHN];
__device__ float  g_S[NCH * CHN];
__device__ float  g_P[NCH * CHN];

// ---------------------------------------------------------------------------
// f32 -> f16 conversion, vectorized
// ---------------------------------------------------------------------------
__global__ __launch_bounds__(256) void f2h_kernel(const float4* __restrict__ src,
                                                  uint2* __restrict__ dst, int n4)
{
    int i = blockIdx.x * blockDim.x + threadIdx.x;
    const int stride = gridDim.x * blockDim.x;
    for (; i < n4; i += stride) {
        float4 v = src[i];
        __half2 h0 = __floats2half2_rn(v.x, v.y);
        __half2 h1 = __floats2half2_rn(v.z, v.w);
        uint2 o;
        o.x = *reinterpret_cast<unsigned*>(&h0);
        o.y = *reinterpret_cast<unsigned*>(&h1);
        dst[i] = o;
    }
}

// ---------------------------------------------------------------------------
// FP16 tensor-core GEMM + sigmoid + FUSED chunk-scan epilogue.
//   g_lamh = sigmoid(X @ W^T + b);  g_A/g_S = per-chunk scan summaries.
// A-tile k-slices for cols [n0b,n0b+256) pass through smem at stages
// kt in [8*bx, 8*bx+8) -> captured into xkeep. Epilogue scans columns
// from smem (lam tile aliases dead pipeline buffers).
// ---------------------------------------------------------------------------
#define BM 128
#define BN 256
#define BK 32
#define PITH 40
#define NSTG 4
#define A_STGH (BM * PITH)
#define B_STGH (BN * PITH)
#define SMEM_HALVES (NSTG * (A_STGH + B_STGH))   // 61440 halves = 120 KB
#define XP 264                                    // xkeep pitch (halves)
#define LP 264                                    // lam-tile pitch (halves)
#define XKEEP_HALVES (BM * XP)                    // 33792 halves = 66 KB
#define SMEM_TOTAL_HALVES (SMEM_HALVES + XKEEP_HALVES)
#define NKT (Dd / BK)

__device__ __forceinline__ void cp16s(uint32_t smem_dst, const void* gmem_src) {
    asm volatile("cp.async.cg.shared.global [%0], [%1], 16;\n"
                 :: "r"(smem_dst), "l"(gmem_src));
}
__device__ __forceinline__ void cp_commit() {
    asm volatile("cp.async.commit_group;\n");
}
template <int N>
__device__ __forceinline__ void cp_wait() {
    asm volatile("cp.async.wait_group %0;\n" :: "n"(N));
}
__device__ __forceinline__ void mma_f16(float* d, const unsigned* a, const unsigned* b) {
    asm volatile(
        "mma.sync.aligned.m16n8k16.row.col.f32.f16.f16.f32 "
        "{%0,%1,%2,%3}, {%4,%5,%6,%7}, {%8,%9}, {%0,%1,%2,%3};\n"
        : "+f"(d[0]), "+f"(d[1]), "+f"(d[2]), "+f"(d[3])
        : "r"(a[0]), "r"(a[1]), "r"(a[2]), "r"(a[3]), "r"(b[0]), "r"(b[1]));
}
__device__ __forceinline__ void ldsm_x4(unsigned* r, uint32_t addr) {
    asm volatile("ldmatrix.sync.aligned.m8n8.x4.shared.b16 {%0,%1,%2,%3}, [%4];"
        : "=r"(r[0]), "=r"(r[1]), "=r"(r[2]), "=r"(r[3]) : "r"(addr));
}
__device__ __forceinline__ void ldsm_x2(unsigned* r, uint32_t addr) {
    asm volatile("ldmatrix.sync.aligned.m8n8.x2.shared.b16 {%0,%1}, [%2];"
        : "=r"(r[0]), "=r"(r[1]) : "r"(addr));
}

extern __shared__ __half smemh[];

__global__ __launch_bounds__(256, 1) void gemm_sigmoid_scan_f16(
    const float* __restrict__ bias)
{
    const int tid  = threadIdx.x;
    const int lane = tid & 31;
    const int wid  = tid >> 5;
    const int wm0  = (wid & 1) * 64;
    const int wn0  = (wid >> 1) * 64;
    const int g    = lane >> 2;
    const int q    = lane & 3;
    const int m0b  = blockIdx.y * BM;
    const int n0b  = blockIdx.x * BN;
    const int kt0  = blockIdx.x * 8;      // stages whose k-slice == our columns

    __half* xkeep    = smemh + SMEM_HALVES;       // persistent x slice
    __half* lam_tile = smemh;                     // aliases pipeline (post-loop)

    const uint32_t sA = (uint32_t)__cvta_generic_to_shared(smemh);
    const uint32_t sB = sA + NSTG * A_STGH * 2;

    const int arow = ((lane & 8) ? 8 : 0) + (lane & 7);
    const int akad = (lane & 16) ? 8 : 0;
    const int brow = lane & 7;
    const int bkad = (lane & 8) ? 8 : 0;

    float acc[4][8][4];
    #pragma unroll
    for (int mi = 0; mi < 4; mi++)
        #pragma unroll
        for (int ni = 0; ni < 8; ni++)
            #pragma unroll
            for (int r = 0; r < 4; r++)
                acc[mi][ni][r] = 0.0f;

    auto load_stage = [&](int kt) {
        const int slot = kt & (NSTG - 1);
        const int k0   = kt * BK;
        const uint32_t abase = sA + slot * A_STGH * 2;
        const uint32_t bbase = sB + slot * B_STGH * 2;
        #pragma unroll
        for (int i = 0; i < 6; i++) {
            int idx = tid + i * 256;
            if (idx < 512) {
                int r = idx >> 2, c = idx & 3;
                cp16s(abase + (r * PITH + c * 8) * 2,
                      &g_Xh[(size_t)(m0b + r) * Dd + k0 + c * 8]);
            } else {
                int j = idx - 512;
                int r = j >> 2, c = j & 3;
                cp16s(bbase + (r * PITH + c * 8) * 2,
                      &g_Wh[(size_t)(n0b + r) * Dd + k0 + c * 8]);
            }
        }
        cp_commit();
    };

    load_stage(0);
    load_stage(1);
    load_stage(2);

    for (int kt = 0; kt < NKT; kt++) {
        if (kt + 3 < NKT) load_stage(kt + 3);
        else cp_commit();                  // keep group accounting exact at tail
        cp_wait<3>();
        __syncthreads();

        const int slot = kt & (NSTG - 1);
        const uint32_t aslot = sA + slot * A_STGH * 2;
        const uint32_t bslot = sB + slot * B_STGH * 2;

        // capture x slice for our output columns (8 stages per CTA)
        if ((unsigned)(kt - kt0) < 8u) {
            const int koff = (kt - kt0) * 32;
            const __half* asl = smemh + slot * A_STGH;
            #pragma unroll
            for (int i = 0; i < 2; i++) {
                int idx = tid + i * 256;          // 0..511
                int r = idx >> 2, c = idx & 3;
                uint4 v = *(const uint4*)&asl[r * PITH + c * 8];
                *(uint4*)&xkeep[r * XP + koff + c * 8] = v;
            }
        }

        #pragma unroll
        for (int kf = 0; kf < BK; kf += 16) {
            unsigned af[4][4], bf[8][2];
            #pragma unroll
            for (int mi = 0; mi < 4; mi++)
                ldsm_x4(af[mi],
                        aslot + ((wm0 + mi * 16 + arow) * PITH + kf + akad) * 2);
            #pragma unroll
            for (int ni = 0; ni < 8; ni++)
                ldsm_x2(bf[ni],
                        bslot + ((wn0 + ni * 8 + brow) * PITH + kf + bkad) * 2);
            #pragma unroll
            for (int mi = 0; mi < 4; mi++)
                #pragma unroll
                for (int ni = 0; ni < 8; ni++)
                    mma_f16(acc[mi][ni], af[mi], bf[ni]);
        }
        __syncthreads();
    }

    // ---- epilogue: bias+sigmoid -> gmem AND lam smem tile ----
    #pragma unroll
    for (int ni = 0; ni < 8; ni++) {
        const int cl = wn0 + ni * 8 + 2 * q;      // local col (even)
        const int c0 = n0b + cl;
        const float b0 = bias[c0];
        const float b1 = bias[c0 + 1];
        #pragma unroll
        for (int mi = 0; mi < 4; mi++) {
            const int rl = wm0 + mi * 16 + g;     // local row
            const int r0 = m0b + rl;
            float z0 = acc[mi][ni][0] + b0, z1 = acc[mi][ni][1] + b1;
            float z2 = acc[mi][ni][2] + b0, z3 = acc[mi][ni][3] + b1;
            __half2 h0 = __floats2half2_rn(1.0f / (1.0f + __expf(-z0)),
                                           1.0f / (1.0f + __expf(-z1)));
            __half2 h1 = __floats2half2_rn(1.0f / (1.0f + __expf(-z2)),
                                           1.0f / (1.0f + __expf(-z3)));
            *(__half2*)&g_lamh[(size_t)r0 * Dd + c0]       = h0;
            *(__half2*)&g_lamh[(size_t)(r0 + 8) * Dd + c0] = h1;
            *(__half2*)&lam_tile[rl * LP + cl]       = h0;
            *(__half2*)&lam_tile[(rl + 8) * LP + cl] = h1;
        }
    }
    __syncthreads();

    // ---- fused scan1: thread t scans column t (2 chunks of 64 rows) ----
    {
        const int t  = tid;                        // local col 0..255
        const int b  = m0b / Kk;                   // batch
        const int cg = (m0b % Kk) / LCH;           // first chunk index
        const int dg = n0b + t;                    // global channel
        const int chn = b * Dd + dg;

        float A0 = 1.0f, S0 = 0.0f;
        #pragma unroll 8
        for (int r = 0; r < 64; r++) {
            float lam = __half2float(lam_tile[r * LP + t]);
            float xv  = __half2float(xkeep[r * XP + t]);
            S0 = fmaf(lam, S0 - xv, xv);
            A0 *= lam;
        }
        g_A[cg * CHN + chn] = A0;
        g_S[cg * CHN + chn] = S0;

        float A1 = 1.0f, S1 = 0.0f;
        #pragma unroll 8
        for (int r = 64; r < 128; r++) {
            float lam = __half2float(lam_tile[r * LP + t]);
            float xv  = __half2float(xkeep[r * XP + t]);
            S1 = fmaf(lam, S1 - xv, xv);
            A1 *= lam;
        }
        g_A[(cg + 1) * CHN + chn] = A1;
        g_S[(cg + 1) * CHN + chn] = S1;
    }
}

// ---------------------------------------------------------------------------
// Scan phase 2: 128 chunks per channel; one warp per channel, 4 chunks/lane.
// ---------------------------------------------------------------------------
__global__ __launch_bounds__(256) void scan_phase2()
{
    const int lane = threadIdx.x & 31;
    const int ch   = blockIdx.x * 8 + (threadIdx.x >> 5);

    float A[4], S[4];
    #pragma unroll
    for (int j = 0; j < 4; j++) {
        A[j] = g_A[(4 * lane + j) * CHN + ch];
        S[j] = g_S[(4 * lane + j) * CHN + ch];
    }
    float Ac = A[0], Sc = S[0];
    #pragma unroll
    for (int j = 1; j < 4; j++) { Sc = fmaf(A[j], Sc, S[j]); Ac *= A[j]; }

    #pragma unroll
    for (int off = 1; off < 32; off <<= 1) {
        float Ap = __shfl_up_sync(0xffffffffu, Ac, off);
        float Sp = __shfl_up_sync(0xffffffffu, Sc, off);
        if (lane >= off) { Sc = fmaf(Ac, Sp, Sc); Ac *= Ap; }
    }
    float Pbase = __shfl_up_sync(0xffffffffu, Sc, 1);
    if (lane == 0) Pbase = 0.0f;

    float s = Pbase;
    #pragma unroll
    for (int j = 0; j < 4; j++) {
        g_P[(4 * lane + j) * CHN + ch] = s;
        s = fmaf(A[j], s, S[j]);
    }
}

// ---------------------------------------------------------------------------
// Scan phase 3: re-scan each chunk from its prefix; write fp32 output.
// ---------------------------------------------------------------------------
__global__ __launch_bounds__(256) void scan_phase3(float* __restrict__ out)
{
    const int d2 = blockIdx.x * 256 + threadIdx.x;
    const int d  = d2 * 2;
    const int b  = blockIdx.y;
    const int c  = blockIdx.z;
    const int ch = b * Dd + d;
    size_t base = ((size_t)(b * Kk + c * LCH)) * Dd + d;

    float2 p = *(const float2*)&g_P[c * CHN + ch];
    float s0 = p.x, s1 = p.y;
    #pragma unroll 8
    for (int k = 0; k < LCH; k++) {
        size_t idx = base + (size_t)k * Dd;
        float2 lam = __half22float2(*(const __half2*)&g_lamh[idx]);
        float2 xv  = __half22float2(*(const __half2*)&g_Xh[idx]);
        s0 = fmaf(lam.x, s0 - xv.x, xv.x);
        s1 = fmaf(lam.y, s1 - xv.y, xv.y);
        *(float2*)&out[idx] = make_float2(s0, s1);
    }
}

// ---------------------------------------------------------------------------
extern "C" void kernel_launch(void* const* d_in, const int* in_sizes, int n_in,
                              void* d_out, int out_size)
{
    const float* X    = (const float*)d_in[0];  // [B,K,D]
    const float* W    = (const float*)d_in[1];  // [D,D]
    const float* bias = (const float*)d_in[2];  // [D]
    float* out        = (float*)d_out;          // [B,K,D]

    __half* Xh; cudaGetSymbolAddress((void**)&Xh, g_Xh);
    __half* Wh; cudaGetSymbolAddress((void**)&Wh, g_Wh);
    f2h_kernel<<<1024, 256>>>((const float4*)X, (uint2*)Xh, (Mm * Dd) / 4);
    f2h_kernel<<<256, 256>>>((const float4*)W, (uint2*)Wh, (Dd * Dd) / 4);

    const int smem_bytes = SMEM_TOTAL_HALVES * (int)sizeof(__half);  // ~186 KB
    cudaFuncSetAttribute(gemm_sigmoid_scan_f16,
                         cudaFuncAttributeMaxDynamicSharedMemorySize, smem_bytes);

    dim3 gemm_grid(Dd / BN, Mm / BM);           // (4, 256)
    gemm_sigmoid_scan_f16<<<gemm_grid, 256, smem_bytes>>>(bias);

    scan_phase2<<<CHN / 8, 256>>>();
    dim3 scan_grid(Dd / 512, Bb, NCH);          // (2, 4, 128)
    scan_phase3<<<scan_grid, 256>>>(out);
}

// round 16
// speedup vs baseline: 1.0645x; 1.0095x over previous
#include <cuda_runtime.h>
#include <cuda_fp16.h>
#include <cstdint>
#include <math.h>

// Problem shape (fixed)
#define Bb  4
#define Kk  8192
#define Dd  1024
#define Mm  (Bb * Kk)          // 32768 GEMM rows
#define NCH 128                // scan chunks along K
#define LCH (Kk / NCH)         // 64 steps per chunk
#define CHN (Bb * Dd)          // 4096 independent channels

// Scratch (allocation-free rule: __device__ globals)
// NOTE: summary arrays are [channel][chunk] for coalesced phase-2 access.
__device__ __half g_lamh[(size_t)Mm * Dd];    // 64 MiB fp16 lam
__device__ __half g_Xh[(size_t)Mm * Dd];      // 64 MiB fp16 X
__device__ __half g_Wh[(size_t)Dd * Dd];      // 2 MiB fp16 W
__device__ float  g_A[CHN * NCH];
__device__ float  g_S[CHN * NCH];
__device__ float  g_P[CHN * NCH];

// ---------------------------------------------------------------------------
// f32 -> f16 conversion, vectorized
// ---------------------------------------------------------------------------
__global__ __launch_bounds__(256) void f2h_kernel(const float4* __restrict__ src,
                                                  uint2* __restrict__ dst, int n4)
{
    int i = blockIdx.x * blockDim.x + threadIdx.x;
    const int stride = gridDim.x * blockDim.x;
    for (; i < n4; i += stride) {
        float4 v = src[i];
        __half2 h0 = __floats2half2_rn(v.x, v.y);
        __half2 h1 = __floats2half2_rn(v.z, v.w);
        uint2 o;
        o.x = *reinterpret_cast<unsigned*>(&h0);
        o.y = *reinterpret_cast<unsigned*>(&h1);
        dst[i] = o;
    }
}

// ---------------------------------------------------------------------------
// FP16 tensor-core GEMM + sigmoid + FUSED chunk-scan epilogue.
// Single-barrier 4-stage cp.async mainloop; ldmatrix fragment loads.
// ---------------------------------------------------------------------------
#define BM 128
#define BN 256
#define BK 32
#define PITH 40
#define NSTG 4
#define A_STGH (BM * PITH)
#define B_STGH (BN * PITH)
#define SMEM_HALVES (NSTG * (A_STGH + B_STGH))   // 61440 halves = 120 KB
#define XP 264                                    // xkeep pitch (halves)
#define LP 264                                    // lam-tile pitch (halves)
#define XKEEP_HALVES (BM * XP)                    // 66 KB
#define SMEM_TOTAL_HALVES (SMEM_HALVES + XKEEP_HALVES)
#define NKT (Dd / BK)

__device__ __forceinline__ void cp16s(uint32_t smem_dst, const void* gmem_src) {
    asm volatile("cp.async.cg.shared.global [%0], [%1], 16;\n"
                 :: "r"(smem_dst), "l"(gmem_src));
}
__device__ __forceinline__ void cp_commit() {
    asm volatile("cp.async.commit_group;\n");
}
template <int N>
__device__ __forceinline__ void cp_wait() {
    asm volatile("cp.async.wait_group %0;\n" :: "n"(N));
}
__device__ __forceinline__ void mma_f16(float* d, const unsigned* a, const unsigned* b) {
    asm volatile(
        "mma.sync.aligned.m16n8k16.row.col.f32.f16.f16.f32 "
        "{%0,%1,%2,%3}, {%4,%5,%6,%7}, {%8,%9}, {%0,%1,%2,%3};\n"
        : "+f"(d[0]), "+f"(d[1]), "+f"(d[2]), "+f"(d[3])
        : "r"(a[0]), "r"(a[1]), "r"(a[2]), "r"(a[3]), "r"(b[0]), "r"(b[1]));
}
__device__ __forceinline__ void ldsm_x4(unsigned* r, uint32_t addr) {
    asm volatile("ldmatrix.sync.aligned.m8n8.x4.shared.b16 {%0,%1,%2,%3}, [%4];"
        : "=r"(r[0]), "=r"(r[1]), "=r"(r[2]), "=r"(r[3]) : "r"(addr));
}
__device__ __forceinline__ void ldsm_x2(unsigned* r, uint32_t addr) {
    asm volatile("ldmatrix.sync.aligned.m8n8.x2.shared.b16 {%0,%1}, [%2];"
        : "=r"(r[0]), "=r"(r[1]) : "r"(addr));
}

extern __shared__ __half smemh[];

__global__ __launch_bounds__(256, 1) void gemm_sigmoid_scan_f16(
    const float* __restrict__ bias)
{
    const int tid  = threadIdx.x;
    const int lane = tid & 31;
    const int wid  = tid >> 5;
    const int wm0  = (wid & 1) * 64;
    const int wn0  = (wid >> 1) * 64;
    const int g    = lane >> 2;
    const int q    = lane & 3;
    const int m0b  = blockIdx.y * BM;
    const int n0b  = blockIdx.x * BN;
    const int kt0  = blockIdx.x * 8;      // stages whose k-slice == our columns

    __half* xkeep    = smemh + SMEM_HALVES;       // persistent x slice
    __half* lam_tile = smemh;                     // aliases pipeline (post-loop)

    const uint32_t sA = (uint32_t)__cvta_generic_to_shared(smemh);
    const uint32_t sB = sA + NSTG * A_STGH * 2;

    const int arow = ((lane & 8) ? 8 : 0) + (lane & 7);
    const int akad = (lane & 16) ? 8 : 0;
    const int brow = lane & 7;
    const int bkad = (lane & 8) ? 8 : 0;

    float acc[4][8][4];
    #pragma unroll
    for (int mi = 0; mi < 4; mi++)
        #pragma unroll
        for (int ni = 0; ni < 8; ni++)
            #pragma unroll
            for (int r = 0; r < 4; r++)
                acc[mi][ni][r] = 0.0f;

    auto load_stage = [&](int kt) {
        const int slot = kt & (NSTG - 1);
        const int k0   = kt * BK;
        const uint32_t abase = sA + slot * A_STGH * 2;
        const uint32_t bbase = sB + slot * B_STGH * 2;
        #pragma unroll
        for (int i = 0; i < 6; i++) {
            int idx = tid + i * 256;
            if (idx < 512) {
                int r = idx >> 2, c = idx & 3;
                cp16s(abase + (r * PITH + c * 8) * 2,
                      &g_Xh[(size_t)(m0b + r) * Dd + k0 + c * 8]);
            } else {
                int j = idx - 512;
                int r = j >> 2, c = j & 3;
                cp16s(bbase + (r * PITH + c * 8) * 2,
                      &g_Wh[(size_t)(n0b + r) * Dd + k0 + c * 8]);
            }
        }
        cp_commit();
    };

    load_stage(0);
    load_stage(1);
    load_stage(2);

    for (int kt = 0; kt < NKT; kt++) {
        cp_wait<2>();                      // stage kt landed (3 groups pending)
        __syncthreads();                   // data visible; prior reads done
        if (kt + 3 < NKT) load_stage(kt + 3);   // writes slot (kt-1)&3 — safe
        else cp_commit();                  // keep group accounting exact at tail

        const int slot = kt & (NSTG - 1);
        const uint32_t aslot = sA + slot * A_STGH * 2;
        const uint32_t bslot = sB + slot * B_STGH * 2;

        // capture x slice for our output columns (8 stages per CTA)
        if ((unsigned)(kt - kt0) < 8u) {
            const int koff = (kt - kt0) * 32;
            const __half* asl = smemh + slot * A_STGH;
            #pragma unroll
            for (int i = 0; i < 2; i++) {
                int idx = tid + i * 256;
                int r = idx >> 2, c = idx & 3;
                uint4 v = *(const uint4*)&asl[r * PITH + c * 8];
                *(uint4*)&xkeep[r * XP + koff + c * 8] = v;
            }
        }

        #pragma unroll
        for (int kf = 0; kf < BK; kf += 16) {
            unsigned af[4][4], bf[8][2];
            #pragma unroll
            for (int mi = 0; mi < 4; mi++)
                ldsm_x4(af[mi],
                        aslot + ((wm0 + mi * 16 + arow) * PITH + kf + akad) * 2);
            #pragma unroll
            for (int ni = 0; ni < 8; ni++)
                ldsm_x2(bf[ni],
                        bslot + ((wn0 + ni * 8 + brow) * PITH + kf + bkad) * 2);
            #pragma unroll
            for (int mi = 0; mi < 4; mi++)
                #pragma unroll
                for (int ni = 0; ni < 8; ni++)
                    mma_f16(acc[mi][ni], af[mi], bf[ni]);
        }
    }
    __syncthreads();    // final: all reads done before epilogue reuses smem

    // ---- epilogue: bias+sigmoid -> gmem AND lam smem tile ----
    #pragma unroll
    for (int ni = 0; ni < 8; ni++) {
        const int cl = wn0 + ni * 8 + 2 * q;
        const int c0 = n0b + cl;
        const float b0 = bias[c0];
        const float b1 = bias[c0 + 1];
        #pragma unroll
        for (int mi = 0; mi < 4; mi++) {
            const int rl = wm0 + mi * 16 + g;
            const int r0 = m0b + rl;
            float z0 = acc[mi][ni][0] + b0, z1 = acc[mi][ni][1] + b1;
            float z2 = acc[mi][ni][2] + b0, z3 = acc[mi][ni][3] + b1;
            __half2 h0 = __floats2half2_rn(1.0f / (1.0f + __expf(-z0)),
                                           1.0f / (1.0f + __expf(-z1)));
            __half2 h1 = __floats2half2_rn(1.0f / (1.0f + __expf(-z2)),
                                           1.0f / (1.0f + __expf(-z3)));
            *(__half2*)&g_lamh[(size_t)r0 * Dd + c0]       = h0;
            *(__half2*)&g_lamh[(size_t)(r0 + 8) * Dd + c0] = h1;
            *(__half2*)&lam_tile[rl * LP + cl]       = h0;
            *(__half2*)&lam_tile[(rl + 8) * LP + cl] = h1;
        }
    }
    __syncthreads();

    // ---- fused scan1: thread t scans column t (2 chunks of 64 rows) ----
    {
        const int t   = tid;
        const int b   = m0b / Kk;
        const int cg  = (m0b % Kk) / LCH;          // first chunk index
        const int chn = b * Dd + n0b + t;          // global channel

        float A0 = 1.0f, S0 = 0.0f;
        #pragma unroll 8
        for (int r = 0; r < 64; r++) {
            float lam = __half2float(lam_tile[r * LP + t]);
            float xv  = __half2float(xkeep[r * XP + t]);
            S0 = fmaf(lam, S0 - xv, xv);
            A0 *= lam;
        }
        g_A[chn * NCH + cg] = A0;
        g_S[chn * NCH + cg] = S0;

        float A1 = 1.0f, S1 = 0.0f;
        #pragma unroll 8
        for (int r = 64; r < 128; r++) {
            float lam = __half2float(lam_tile[r * LP + t]);
            float xv  = __half2float(xkeep[r * XP + t]);
            S1 = fmaf(lam, S1 - xv, xv);
            A1 *= lam;
        }
        g_A[chn * NCH + cg + 1] = A1;
        g_S[chn * NCH + cg + 1] = S1;
    }
}

// ---------------------------------------------------------------------------
// Scan phase 2: one warp per channel; [ch][chunk] layout -> float4 coalesced.
// ---------------------------------------------------------------------------
__global__ __launch_bounds__(256) void scan_phase2()
{
    const int lane = threadIdx.x & 31;
    const int ch   = blockIdx.x * 8 + (threadIdx.x >> 5);
    const size_t row = (size_t)ch * NCH;

    float4 Av = *(const float4*)&g_A[row + 4 * lane];
    float4 Sv = *(const float4*)&g_S[row + 4 * lane];
    float A[4] = {Av.x, Av.y, Av.z, Av.w};
    float S[4] = {Sv.x, Sv.y, Sv.z, Sv.w};

    float Ac = A[0], Sc = S[0];
    #pragma unroll
    for (int j = 1; j < 4; j++) { Sc = fmaf(A[j], Sc, S[j]); Ac *= A[j]; }

    #pragma unroll
    for (int off = 1; off < 32; off <<= 1) {
        float Ap = __shfl_up_sync(0xffffffffu, Ac, off);
        float Sp = __shfl_up_sync(0xffffffffu, Sc, off);
        if (lane >= off) { Sc = fmaf(Ac, Sp, Sc); Ac *= Ap; }
    }
    float Pbase = __shfl_up_sync(0xffffffffu, Sc, 1);
    if (lane == 0) Pbase = 0.0f;

    float P[4];
    float s = Pbase;
    #pragma unroll
    for (int j = 0; j < 4; j++) {
        P[j] = s;
        s = fmaf(A[j], s, S[j]);
    }
    *(float4*)&g_P[row + 4 * lane] = make_float4(P[0], P[1], P[2], P[3]);
}

// ---------------------------------------------------------------------------
// Scan phase 3: re-scan each chunk from its prefix; write fp32 output.
// ---------------------------------------------------------------------------
__global__ __launch_bounds__(256) void scan_phase3(float* __restrict__ out)
{
    const int d2 = blockIdx.x * 256 + threadIdx.x;
    const int d  = d2 * 2;
    const int b  = blockIdx.y;
    const int c  = blockIdx.z;
    const int ch = b * Dd + d;
    size_t base = ((size_t)(b * Kk + c * LCH)) * Dd + d;

    float s0 = g_P[(size_t)ch * NCH + c];
    float s1 = g_P[(size_t)(ch + 1) * NCH + c];
    #pragma unroll 8
    for (int k = 0; k < LCH; k++) {
        size_t idx = base + (size_t)k * Dd;
        float2 lam = __half22float2(*(const __half2*)&g_lamh[idx]);
        float2 xv  = __half22float2(*(const __half2*)&g_Xh[idx]);
        s0 = fmaf(lam.x, s0 - xv.x, xv.x);
        s1 = fmaf(lam.y, s1 - xv.y, xv.y);
        *(float2*)&out[idx] = make_float2(s0, s1);
    }
}

// ---------------------------------------------------------------------------
extern "C" void kernel_launch(void* const* d_in, const int* in_sizes, int n_in,
                              void* d_out, int out_size)
{
    const float* X    = (const float*)d_in[0];  // [B,K,D]
    const float* W    = (const float*)d_in[1];  // [D,D]
    const float* bias = (const float*)d_in[2];  // [D]
    float* out        = (float*)d_out;          // [B,K,D]

    __half* Xh; cudaGetSymbolAddress((void**)&Xh, g_Xh);
    __half* Wh; cudaGetSymbolAddress((void**)&Wh, g_Wh);
    f2h_kernel<<<1024, 256>>>((const float4*)X, (uint2*)Xh, (Mm * Dd) / 4);
    f2h_kernel<<<256, 256>>>((const float4*)W, (uint2*)Wh, (Dd * Dd) / 4);

    const int smem_bytes = SMEM_TOTAL_HALVES * (int)sizeof(__half);  // ~186 KB
    cudaFuncSetAttribute(gemm_sigmoid_scan_f16,
                         cudaFuncAttributeMaxDynamicSharedMemorySize, smem_bytes);

    dim3 gemm_grid(Dd / BN, Mm / BM);           // (4, 256)
    gemm_sigmoid_scan_f16<<<gemm_grid, 256, smem_bytes>>>(bias);

    scan_phase2<<<CHN / 8, 256>>>();
    dim3 scan_grid(Dd / 512, Bb, NCH);          // (2, 4, 128)
    scan_phase3<<<scan_grid, 256>>>(out);
}

// round 17
// speedup vs baseline: 1.0759x; 1.0107x over previous
#include <cuda_runtime.h>
#include <cuda_fp16.h>
#include <cstdint>
#include <math.h>

// Problem shape (fixed)
#define Bb  4
#define Kk  8192
#define Dd  1024
#define Mm  (Bb * Kk)          // 32768 GEMM rows
#define NCH 128                // scan chunks along K
#define LCH (Kk / NCH)         // 64 steps per chunk
#define CHN (Bb * Dd)          // 4096 independent channels

// Scratch (allocation-free rule: __device__ globals)
// summary arrays are [channel][chunk] for coalesced phase-2 access.
__device__ __half g_lamh[(size_t)Mm * Dd];    // 64 MiB fp16 lam
__device__ __half g_Xh[(size_t)Mm * Dd];      // 64 MiB fp16 X
__device__ __half g_Wh[(size_t)Dd * Dd];      // 2 MiB fp16 W
__device__ float  g_A[CHN * NCH];
__device__ float  g_S[CHN * NCH];
__device__ float  g_P[CHN * NCH];

// ---------------------------------------------------------------------------
// f32 -> f16 conversion, vectorized
// ---------------------------------------------------------------------------
__global__ __launch_bounds__(256) void f2h_kernel(const float4* __restrict__ src,
                                                  uint2* __restrict__ dst, int n4)
{
    int i = blockIdx.x * blockDim.x + threadIdx.x;
    const int stride = gridDim.x * blockDim.x;
    for (; i < n4; i += stride) {
        float4 v = src[i];
        __half2 h0 = __floats2half2_rn(v.x, v.y);
        __half2 h1 = __floats2half2_rn(v.z, v.w);
        uint2 o;
        o.x = *reinterpret_cast<unsigned*>(&h0);
        o.y = *reinterpret_cast<unsigned*>(&h1);
        dst[i] = o;
    }
}

// ---------------------------------------------------------------------------
// FP16 tensor-core GEMM + sigmoid + FUSED chunk-scan epilogue.
// Single-barrier 4-stage cp.async mainloop; ldmatrix fragment loads.
// xkeep capture AFTER the MMA loop (slot safe until post-(kt+1)-barrier load).
// ---------------------------------------------------------------------------
#define BM 128
#define BN 256
#define BK 32
#define PITH 40
#define NSTG 4
#define A_STGH (BM * PITH)
#define B_STGH (BN * PITH)
#define SMEM_HALVES (NSTG * (A_STGH + B_STGH))   // 61440 halves = 120 KB
#define XP 264                                    // xkeep pitch (halves)
#define LP 264                                    // lam-tile pitch (halves)
#define XKEEP_HALVES (BM * XP)                    // 66 KB
#define SMEM_TOTAL_HALVES (SMEM_HALVES + XKEEP_HALVES)
#define NKT (Dd / BK)

__device__ __forceinline__ void cp16s(uint32_t smem_dst, const void* gmem_src) {
    asm volatile("cp.async.cg.shared.global [%0], [%1], 16;\n"
                 :: "r"(smem_dst), "l"(gmem_src));
}
__device__ __forceinline__ void cp_commit() {
    asm volatile("cp.async.commit_group;\n");
}
template <int N>
__device__ __forceinline__ void cp_wait() {
    asm volatile("cp.async.wait_group %0;\n" :: "n"(N));
}
__device__ __forceinline__ void mma_f16(float* d, const unsigned* a, const unsigned* b) {
    asm volatile(
        "mma.sync.aligned.m16n8k16.row.col.f32.f16.f16.f32 "
        "{%0,%1,%2,%3}, {%4,%5,%6,%7}, {%8,%9}, {%0,%1,%2,%3};\n"
        : "+f"(d[0]), "+f"(d[1]), "+f"(d[2]), "+f"(d[3])
        : "r"(a[0]), "r"(a[1]), "r"(a[2]), "r"(a[3]), "r"(b[0]), "r"(b[1]));
}
__device__ __forceinline__ void ldsm_x4(unsigned* r, uint32_t addr) {
    asm volatile("ldmatrix.sync.aligned.m8n8.x4.shared.b16 {%0,%1,%2,%3}, [%4];"
        : "=r"(r[0]), "=r"(r[1]), "=r"(r[2]), "=r"(r[3]) : "r"(addr));
}
__device__ __forceinline__ void ldsm_x2(unsigned* r, uint32_t addr) {
    asm volatile("ldmatrix.sync.aligned.m8n8.x2.shared.b16 {%0,%1}, [%2];"
        : "=r"(r[0]), "=r"(r[1]) : "r"(addr));
}

extern __shared__ __half smemh[];

__global__ __launch_bounds__(256, 1) void gemm_sigmoid_scan_f16(
    const float* __restrict__ bias)
{
    const int tid  = threadIdx.x;
    const int lane = tid & 31;
    const int wid  = tid >> 5;
    const int wm0  = (wid & 1) * 64;
    const int wn0  = (wid >> 1) * 64;
    const int g    = lane >> 2;
    const int q    = lane & 3;
    const int m0b  = blockIdx.y * BM;
    const int n0b  = blockIdx.x * BN;
    const int kt0  = blockIdx.x * 8;      // stages whose k-slice == our columns

    __half* xkeep    = smemh + SMEM_HALVES;       // persistent x slice
    __half* lam_tile = smemh;                     // aliases pipeline (post-loop)

    const uint32_t sA = (uint32_t)__cvta_generic_to_shared(smemh);
    const uint32_t sB = sA + NSTG * A_STGH * 2;

    const int arow = ((lane & 8) ? 8 : 0) + (lane & 7);
    const int akad = (lane & 16) ? 8 : 0;
    const int brow = lane & 7;
    const int bkad = (lane & 8) ? 8 : 0;

    float acc[4][8][4];
    #pragma unroll
    for (int mi = 0; mi < 4; mi++)
        #pragma unroll
        for (int ni = 0; ni < 8; ni++)
            #pragma unroll
            for (int r = 0; r < 4; r++)
                acc[mi][ni][r] = 0.0f;

    auto load_stage = [&](int kt) {
        const int slot = kt & (NSTG - 1);
        const int k0   = kt * BK;
        const uint32_t abase = sA + slot * A_STGH * 2;
        const uint32_t bbase = sB + slot * B_STGH * 2;
        #pragma unroll
        for (int i = 0; i < 6; i++) {
            int idx = tid + i * 256;
            if (idx < 512) {
                int r = idx >> 2, c = idx & 3;
                cp16s(abase + (r * PITH + c * 8) * 2,
                      &g_Xh[(size_t)(m0b + r) * Dd + k0 + c * 8]);
            } else {
                int j = idx - 512;
                int r = j >> 2, c = j & 3;
                cp16s(bbase + (r * PITH + c * 8) * 2,
                      &g_Wh[(size_t)(n0b + r) * Dd + k0 + c * 8]);
            }
        }
        cp_commit();
    };

    load_stage(0);
    load_stage(1);
    load_stage(2);

    for (int kt = 0; kt < NKT; kt++) {
        cp_wait<2>();                      // stage kt landed
        __syncthreads();                   // data visible; prior reads done
        if (kt + 3 < NKT) load_stage(kt + 3);   // writes slot (kt-1)&3 — safe
        else cp_commit();                  // keep group accounting exact at tail

        const int slot = kt & (NSTG - 1);
        const uint32_t aslot = sA + slot * A_STGH * 2;
        const uint32_t bslot = sB + slot * B_STGH * 2;

        #pragma unroll
        for (int kf = 0; kf < BK; kf += 16) {
            unsigned af[4][4], bf[8][2];
            #pragma unroll
            for (int mi = 0; mi < 4; mi++)
                ldsm_x4(af[mi],
                        aslot + ((wm0 + mi * 16 + arow) * PITH + kf + akad) * 2);
            #pragma unroll
            for (int ni = 0; ni < 8; ni++)
                ldsm_x2(bf[ni],
                        bslot + ((wn0 + ni * 8 + brow) * PITH + kf + bkad) * 2);
            #pragma unroll
            for (int mi = 0; mi < 4; mi++)
                #pragma unroll
                for (int ni = 0; ni < 8; ni++)
                    mma_f16(acc[mi][ni], af[mi], bf[ni]);
        }

        // capture x slice AFTER MMAs (slot kt safe until the load issued
        // after the kt+1 barrier, which targets slot kt&3)
        if ((unsigned)(kt - kt0) < 8u) {
            const int koff = (kt - kt0) * 32;
            const __half* asl = smemh + slot * A_STGH;
            #pragma unroll
            for (int i = 0; i < 2; i++) {
                int idx = tid + i * 256;
                int r = idx >> 2, c = idx & 3;
                uint4 v = *(const uint4*)&asl[r * PITH + c * 8];
                *(uint4*)&xkeep[r * XP + koff + c * 8] = v;
            }
        }
    }
    __syncthreads();    // all reads done before epilogue reuses smem

    // ---- epilogue: bias+sigmoid -> gmem AND lam smem tile ----
    #pragma unroll
    for (int ni = 0; ni < 8; ni++) {
        const int cl = wn0 + ni * 8 + 2 * q;
        const int c0 = n0b + cl;
        const float b0 = bias[c0];
        const float b1 = bias[c0 + 1];
        #pragma unroll
        for (int mi = 0; mi < 4; mi++) {
            const int rl = wm0 + mi * 16 + g;
            const int r0 = m0b + rl;
            float z0 = acc[mi][ni][0] + b0, z1 = acc[mi][ni][1] + b1;
            float z2 = acc[mi][ni][2] + b0, z3 = acc[mi][ni][3] + b1;
            __half2 h0 = __floats2half2_rn(1.0f / (1.0f + __expf(-z0)),
                                           1.0f / (1.0f + __expf(-z1)));
            __half2 h1 = __floats2half2_rn(1.0f / (1.0f + __expf(-z2)),
                                           1.0f / (1.0f + __expf(-z3)));
            *(__half2*)&g_lamh[(size_t)r0 * Dd + c0]       = h0;
            *(__half2*)&g_lamh[(size_t)(r0 + 8) * Dd + c0] = h1;
            *(__half2*)&lam_tile[rl * LP + cl]       = h0;
            *(__half2*)&lam_tile[(rl + 8) * LP + cl] = h1;
        }
    }
    __syncthreads();

    // ---- fused scan1: thread t scans column t (2 chunks of 64 rows) ----
    {
        const int t   = tid;
        const int b   = m0b / Kk;
        const int cg  = (m0b % Kk) / LCH;          // first chunk index
        const int chn = b * Dd + n0b + t;          // global channel

        float A0 = 1.0f, S0 = 0.0f;
        #pragma unroll 8
        for (int r = 0; r < 64; r++) {
            float lam = __half2float(lam_tile[r * LP + t]);
            float xv  = __half2float(xkeep[r * XP + t]);
            S0 = fmaf(lam, S0 - xv, xv);
            A0 *= lam;
        }
        g_A[chn * NCH + cg] = A0;
        g_S[chn * NCH + cg] = S0;

        float A1 = 1.0f, S1 = 0.0f;
        #pragma unroll 8
        for (int r = 64; r < 128; r++) {
            float lam = __half2float(lam_tile[r * LP + t]);
            float xv  = __half2float(xkeep[r * XP + t]);
            S1 = fmaf(lam, S1 - xv, xv);
            A1 *= lam;
        }
        g_A[chn * NCH + cg + 1] = A1;
        g_S[chn * NCH + cg + 1] = S1;
    }
}

// ---------------------------------------------------------------------------
// Scan phase 2: one warp per channel; [ch][chunk] layout -> float4 coalesced.
// ---------------------------------------------------------------------------
__global__ __launch_bounds__(256) void scan_phase2()
{
    const int lane = threadIdx.x & 31;
    const int ch   = blockIdx.x * 8 + (threadIdx.x >> 5);
    const size_t row = (size_t)ch * NCH;

    float4 Av = *(const float4*)&g_A[row + 4 * lane];
    float4 Sv = *(const float4*)&g_S[row + 4 * lane];
    float A[4] = {Av.x, Av.y, Av.z, Av.w};
    float S[4] = {Sv.x, Sv.y, Sv.z, Sv.w};

    float Ac = A[0], Sc = S[0];
    #pragma unroll
    for (int j = 1; j < 4; j++) { Sc = fmaf(A[j], Sc, S[j]); Ac *= A[j]; }

    #pragma unroll
    for (int off = 1; off < 32; off <<= 1) {
        float Ap = __shfl_up_sync(0xffffffffu, Ac, off);
        float Sp = __shfl_up_sync(0xffffffffu, Sc, off);
        if (lane >= off) { Sc = fmaf(Ac, Sp, Sc); Ac *= Ap; }
    }
    float Pbase = __shfl_up_sync(0xffffffffu, Sc, 1);
    if (lane == 0) Pbase = 0.0f;

    float P[4];
    float s = Pbase;
    #pragma unroll
    for (int j = 0; j < 4; j++) {
        P[j] = s;
        s = fmaf(A[j], s, S[j]);
    }
    *(float4*)&g_P[row + 4 * lane] = make_float4(P[0], P[1], P[2], P[3]);
}

// ---------------------------------------------------------------------------
// Scan phase 3: re-scan each chunk from its prefix; deeper unroll for MLP.
// ---------------------------------------------------------------------------
__global__ __launch_bounds__(256) void scan_phase3(float* __restrict__ out)
{
    const int d2 = blockIdx.x * 256 + threadIdx.x;
    const int d  = d2 * 2;
    const int b  = blockIdx.y;
    const int c  = blockIdx.z;
    const int ch = b * Dd + d;
    size_t base = ((size_t)(b * Kk + c * LCH)) * Dd + d;

    float s0 = g_P[(size_t)ch * NCH + c];
    float s1 = g_P[(size_t)(ch + 1) * NCH + c];
    #pragma unroll 16
    for (int k = 0; k < LCH; k++) {
        size_t idx = base + (size_t)k * Dd;
        float2 lam = __half22float2(*(const __half2*)&g_lamh[idx]);
        float2 xv  = __half22float2(*(const __half2*)&g_Xh[idx]);
        s0 = fmaf(lam.x, s0 - xv.x, xv.x);
        s1 = fmaf(lam.y, s1 - xv.y, xv.y);
        *(float2*)&out[idx] = make_float2(s0, s1);
    }
}

// ---------------------------------------------------------------------------
extern "C" void kernel_launch(void* const* d_in, const int* in_sizes, int n_in,
                              void* d_out, int out_size)
{
    const float* X    = (const float*)d_in[0];  // [B,K,D]
    const float* W    = (const float*)d_in[1];  // [D,D]
    const float* bias = (const float*)d_in[2];  // [D]
    float* out        = (float*)d_out;          // [B,K,D]

    __half* Xh; cudaGetSymbolAddress((void**)&Xh, g_Xh);
    __half* Wh; cudaGetSymbolAddress((void**)&Wh, g_Wh);
    f2h_kernel<<<2048, 256>>>((const float4*)X, (uint2*)Xh, (Mm * Dd) / 4);
    f2h_kernel<<<256, 256>>>((const float4*)W, (uint2*)Wh, (Dd * Dd) / 4);

    const int smem_bytes = SMEM_TOTAL_HALVES * (int)sizeof(__half);  // ~186 KB
    cudaFuncSetAttribute(gemm_sigmoid_scan_f16,
                         cudaFuncAttributeMaxDynamicSharedMemorySize, smem_bytes);

    dim3 gemm_grid(Dd / BN, Mm / BM);           // (4, 256)
    gemm_sigmoid_scan_f16<<<gemm_grid, 256, smem_bytes>>>(bias);

    scan_phase2<<<CHN / 8, 256>>>();
    dim3 scan_grid(Dd / 512, Bb, NCH);          // (2, 4, 128)
    scan_phase3<<<scan_grid, 256>>>(out);
}